// round 3
// baseline (speedup 1.0000x reference)
#include <cuda_runtime.h>
#include <math.h>
#include <stdint.h>

// SAGAN SelfAttention: B=16, C=512, H=W=64, HW=4096, HW4=1024, C8=64, C2=256
#define NB 16

__device__ __align__(128) float g_theta[(size_t)NB * 4096 * 64];   // [b][p][c]
__device__ __align__(128) float g_phi  [(size_t)NB * 64 * 1024];   // [b][c][m]
__device__ __align__(128) float g_gv   [(size_t)NB * 1024 * 256];  // [b][m][co]
__device__ __align__(128) float g_ag   [(size_t)NB * 4096 * 256];  // [b][p][co]

__device__ __forceinline__ unsigned f2tf(float f) {
    unsigned r; asm("cvt.rna.tf32.f32 %0,%1;" : "=r"(r) : "f"(f)); return r;
}
__device__ __forceinline__ void tf32_split(float f, unsigned& hi, unsigned& lo) {
    asm("cvt.rna.tf32.f32 %0,%1;" : "=r"(hi) : "f"(f));
    float rem = f - __uint_as_float(hi);
    asm("cvt.rna.tf32.f32 %0,%1;" : "=r"(lo) : "f"(rem));
}
__device__ __forceinline__ void mma_tf32(float d[4], const unsigned a[4], const unsigned b[2]) {
    asm("mma.sync.aligned.m16n8k8.row.col.f32.tf32.tf32.f32 "
        "{%0,%1,%2,%3},{%4,%5,%6,%7},{%8,%9},{%0,%1,%2,%3};"
        : "+f"(d[0]), "+f"(d[1]), "+f"(d[2]), "+f"(d[3])
        : "r"(a[0]), "r"(a[1]), "r"(a[2]), "r"(a[3]), "r"(b[0]), "r"(b[1]));
}

// ---------------------------------------------------------------------------
// Conv GEMM: rows = out-channels, cols = 128 spatial positions (2 image rows).
// EPI=0: M=128 (theta rows 0-63 transposed store; phi rows 64-127 pooled), 3xTF32
// EPI=1: M=256 (g), plain tf32, pooled store. 256 thr, warp grid 2x4, warp 64x32.
// ---------------------------------------------------------------------------
template <int EPI>
__global__ void __launch_bounds__(256)
conv_kernel(const float* __restrict__ x,
            const float* __restrict__ wA, const float* __restrict__ wB,
            const float* __restrict__ bA, const float* __restrict__ bB)
{
    __shared__ union {
        struct { float A[128][36]; float Bm[32][132]; } gm;
        float stage[128][66];
    } sm;
    const int tid = threadIdx.x, lane = tid & 31, wid = tid >> 5;
    const int gq = lane >> 2, tq = lane & 3;
    const int wm = wid & 1, wn = wid >> 1;
    const int b = blockIdx.z, tb = blockIdx.x;
    const int n0 = tb * 128, m0 = blockIdx.y * 128;
    const float* xb = x + ((size_t)b << 21);

    float acc[4][4][4];
#pragma unroll
    for (int i = 0; i < 4; i++)
#pragma unroll
        for (int j = 0; j < 4; j++)
#pragma unroll
            for (int k = 0; k < 4; k++) acc[i][j][k] = 0.f;

    for (int k0 = 0; k0 < 512; k0 += 32) {
#pragma unroll
        for (int p = 0; p < 4; p++) {
            int idx = tid + p * 256, r = idx >> 3, c4 = (idx & 7) << 2;
            int R = m0 + r;
            const float* wp = (EPI == 0)
                ? (R < 64 ? wA + (size_t)R * 512 : wB + (size_t)(R - 64) * 512)
                : (wA + (size_t)R * 512);
            *(float4*)&sm.gm.A[r][c4] = *(const float4*)(wp + k0 + c4);
        }
#pragma unroll
        for (int p = 0; p < 4; p++) {
            int idx = tid + p * 256, r = idx >> 5, c4 = (idx & 31) << 2;
            *(float4*)&sm.gm.Bm[r][c4] = *(const float4*)(xb + (size_t)(k0 + r) * 4096 + n0 + c4);
        }
        __syncthreads();
#pragma unroll
        for (int k8 = 0; k8 < 4; k8++) {
            const int kk = k8 * 8;
            unsigned ahi[4][4], alo[4][4], bhi[4][2], blo[4][2];
#pragma unroll
            for (int mt = 0; mt < 4; mt++) {
                int r0 = wm * 64 + mt * 16 + gq;
                float a0 = sm.gm.A[r0][kk + tq],     a1 = sm.gm.A[r0 + 8][kk + tq];
                float a2 = sm.gm.A[r0][kk + tq + 4], a3 = sm.gm.A[r0 + 8][kk + tq + 4];
                if constexpr (EPI == 0) {
                    tf32_split(a0, ahi[mt][0], alo[mt][0]); tf32_split(a1, ahi[mt][1], alo[mt][1]);
                    tf32_split(a2, ahi[mt][2], alo[mt][2]); tf32_split(a3, ahi[mt][3], alo[mt][3]);
                } else {
                    ahi[mt][0] = f2tf(a0); ahi[mt][1] = f2tf(a1);
                    ahi[mt][2] = f2tf(a2); ahi[mt][3] = f2tf(a3);
                }
            }
#pragma unroll
            for (int nt = 0; nt < 4; nt++) {
                int c0 = wn * 32 + nt * 8 + gq;
                float b0 = sm.gm.Bm[kk + tq][c0], b1 = sm.gm.Bm[kk + tq + 4][c0];
                if constexpr (EPI == 0) {
                    tf32_split(b0, bhi[nt][0], blo[nt][0]);
                    tf32_split(b1, bhi[nt][1], blo[nt][1]);
                } else {
                    bhi[nt][0] = f2tf(b0); bhi[nt][1] = f2tf(b1);
                }
            }
#pragma unroll
            for (int mt = 0; mt < 4; mt++)
#pragma unroll
                for (int nt = 0; nt < 4; nt++) {
                    mma_tf32(acc[mt][nt], ahi[mt], bhi[nt]);
                    if constexpr (EPI == 0) {
                        mma_tf32(acc[mt][nt], ahi[mt], blo[nt]);
                        mma_tf32(acc[mt][nt], alo[mt], bhi[nt]);
                    }
                }
        }
        __syncthreads();
    }

#pragma unroll
    for (int mt = 0; mt < 4; mt++) {
        int R0 = m0 + wm * 64 + mt * 16 + gq, R1 = R0 + 8;
        float bv0 = (EPI == 0) ? (R0 < 64 ? bA[R0] : bB[R0 - 64]) : bA[R0];
        float bv1 = (EPI == 0) ? (R1 < 64 ? bA[R1] : bB[R1 - 64]) : bA[R1];
#pragma unroll
        for (int nt = 0; nt < 4; nt++) {
            acc[mt][nt][0] += bv0; acc[mt][nt][1] += bv0;
            acc[mt][nt][2] += bv1; acc[mt][nt][3] += bv1;
        }
    }

    if constexpr (EPI == 0) {
        if (wm == 0) {  // theta -> [b][p][c]
#pragma unroll
            for (int mt = 0; mt < 4; mt++) {
                int R0 = mt * 16 + gq;
#pragma unroll
                for (int nt = 0; nt < 4; nt++) {
                    int col = n0 + wn * 32 + nt * 8 + 2 * tq;
                    float* tp = g_theta + ((size_t)b * 4096 + col) * 64;
                    tp[R0] = acc[mt][nt][0];      tp[64 + R0] = acc[mt][nt][1];
                    tp[R0 + 8] = acc[mt][nt][2];  tp[64 + R0 + 8] = acc[mt][nt][3];
                }
            }
        } else {        // phi: w-pool in-register, stage for h-pool
#pragma unroll
            for (int mt = 0; mt < 4; mt++) {
                int r0 = 64 + mt * 16 + gq;
#pragma unroll
                for (int nt = 0; nt < 4; nt++) {
                    int j = wn * 16 + nt * 4 + tq;
                    sm.stage[r0][j]     = fmaxf(acc[mt][nt][0], acc[mt][nt][1]);
                    sm.stage[r0 + 8][j] = fmaxf(acc[mt][nt][2], acc[mt][nt][3]);
                }
            }
        }
        __syncthreads();
        for (int idx = tid; idx < 64 * 32; idx += 256) {
            int co = idx >> 5, wp = idx & 31;
            float v = fmaxf(sm.stage[64 + co][wp], sm.stage[64 + co][wp + 32]);
            g_phi[((size_t)b * 64 + co) * 1024 + tb * 32 + wp] = v;
        }
    } else {
#pragma unroll
        for (int mt = 0; mt < 4; mt++) {
            int r0 = wm * 64 + mt * 16 + gq;
#pragma unroll
            for (int nt = 0; nt < 4; nt++) {
                int j = wn * 16 + nt * 4 + tq;
                sm.stage[r0][j]     = fmaxf(acc[mt][nt][0], acc[mt][nt][1]);
                sm.stage[r0 + 8][j] = fmaxf(acc[mt][nt][2], acc[mt][nt][3]);
            }
        }
        __syncthreads();
        for (int idx = tid; idx < 128 * 32; idx += 256) {
            int wp = idx >> 7, r = idx & 127;
            float v = fmaxf(sm.stage[r][wp], sm.stage[r][wp + 32]);
            g_gv[((size_t)b * 1024 + tb * 32 + wp) * 256 + m0 + r] = v;
        }
    }
}

// ---------------------------------------------------------------------------
// Flash attention: block = (b, 64 query rows). 8 warps: wm 0-1 (rows), wn 0-3.
// S 64x128 (warp 32x32, 3xTF32) -> online softmax -> O 64x256 (warp 32x64, tf32).
// dyn smem: Th[64][68] | Ps[64][132] | union(Ph[64][132], Gs[32][260]) | red[4][64]
// ---------------------------------------------------------------------------
__global__ void __launch_bounds__(256)
attn_kernel()
{
    extern __shared__ float smema[];
    float (*Th)[68]  = (float(*)[68])smema;
    float (*Ps)[132] = (float(*)[132])(smema + 64 * 68);
    float* Xu        = smema + 64 * 68 + 64 * 132;
    float (*Ph)[132] = (float(*)[132])Xu;
    float (*Gs)[260] = (float(*)[260])Xu;
    float (*red)[64] = (float(*)[64])(Xu + 64 * 132);

    const int tid = threadIdx.x, lane = tid & 31, wid = tid >> 5;
    const int gq = lane >> 2, tq = lane & 3;
    const int wm = wid >> 2, wn = wid & 3;
    const int b = blockIdx.y, p0 = blockIdx.x * 64;

#pragma unroll
    for (int p = 0; p < 4; p++) {
        int idx = tid + p * 256, r = idx >> 4, c4 = (idx & 15) << 2;
        *(float4*)&Th[r][c4] = *(const float4*)(g_theta + ((size_t)b * 4096 + p0 + r) * 64 + c4);
    }

    float oacc[2][8][4];
#pragma unroll
    for (int i = 0; i < 2; i++)
#pragma unroll
        for (int j = 0; j < 8; j++)
#pragma unroll
            for (int k = 0; k < 4; k++) oacc[i][j][k] = 0.f;
    float rmax[2][2] = {{-INFINITY, -INFINITY}, {-INFINITY, -INFINITY}};
    float rsum[2][2] = {{0.f, 0.f}, {0.f, 0.f}};

    for (int mc = 0; mc < 8; mc++) {
        const int mc0 = mc * 128;
        __syncthreads();
#pragma unroll
        for (int p = 0; p < 8; p++) {
            int idx = tid + p * 256, r = idx >> 5, c4 = (idx & 31) << 2;
            *(float4*)&Ph[r][c4] = *(const float4*)(g_phi + ((size_t)b * 64 + r) * 1024 + mc0 + c4);
        }
        __syncthreads();

        float sacc[2][4][4];
#pragma unroll
        for (int i = 0; i < 2; i++)
#pragma unroll
            for (int j = 0; j < 4; j++)
#pragma unroll
                for (int k = 0; k < 4; k++) sacc[i][j][k] = 0.f;
#pragma unroll
        for (int k8 = 0; k8 < 8; k8++) {
            const int kk = k8 * 8;
            unsigned ahi[2][4], alo[2][4], bhi[4][2], blo[4][2];
#pragma unroll
            for (int mt = 0; mt < 2; mt++) {
                int r0 = wm * 32 + mt * 16 + gq;
                tf32_split(Th[r0][kk + tq],         ahi[mt][0], alo[mt][0]);
                tf32_split(Th[r0 + 8][kk + tq],     ahi[mt][1], alo[mt][1]);
                tf32_split(Th[r0][kk + tq + 4],     ahi[mt][2], alo[mt][2]);
                tf32_split(Th[r0 + 8][kk + tq + 4], ahi[mt][3], alo[mt][3]);
            }
#pragma unroll
            for (int nt = 0; nt < 4; nt++) {
                int c0 = wn * 32 + nt * 8 + gq;
                tf32_split(Ph[kk + tq][c0],     bhi[nt][0], blo[nt][0]);
                tf32_split(Ph[kk + tq + 4][c0], bhi[nt][1], blo[nt][1]);
            }
#pragma unroll
            for (int mt = 0; mt < 2; mt++)
#pragma unroll
                for (int nt = 0; nt < 4; nt++) {
                    mma_tf32(sacc[mt][nt], ahi[mt], bhi[nt]);
                    mma_tf32(sacc[mt][nt], ahi[mt], blo[nt]);
                    mma_tf32(sacc[mt][nt], alo[mt], bhi[nt]);
                }
        }

        // online softmax
        float cmax[2][2];
#pragma unroll
        for (int mt = 0; mt < 2; mt++)
#pragma unroll
            for (int h = 0; h < 2; h++) {
                float m_ = -INFINITY;
#pragma unroll
                for (int nt = 0; nt < 4; nt++)
                    m_ = fmaxf(m_, fmaxf(sacc[mt][nt][2 * h], sacc[mt][nt][2 * h + 1]));
                m_ = fmaxf(m_, __shfl_xor_sync(0xffffffffu, m_, 1));
                m_ = fmaxf(m_, __shfl_xor_sync(0xffffffffu, m_, 2));
                cmax[mt][h] = m_;
            }
        if (tq == 0)
#pragma unroll
            for (int mt = 0; mt < 2; mt++)
#pragma unroll
                for (int h = 0; h < 2; h++)
                    red[wn][wm * 32 + mt * 16 + gq + 8 * h] = cmax[mt][h];
        __syncthreads();
        float nmax[2][2], fct[2][2];
#pragma unroll
        for (int mt = 0; mt < 2; mt++)
#pragma unroll
            for (int h = 0; h < 2; h++) {
                int rl = wm * 32 + mt * 16 + gq + 8 * h;
                float m_ = fmaxf(fmaxf(red[0][rl], red[1][rl]), fmaxf(red[2][rl], red[3][rl]));
                float nm = fmaxf(rmax[mt][h], m_);
                fct[mt][h] = __expf(rmax[mt][h] - nm);
                rmax[mt][h] = nm; nmax[mt][h] = nm;
            }
        float lsum[2][2] = {{0.f, 0.f}, {0.f, 0.f}};
#pragma unroll
        for (int mt = 0; mt < 2; mt++) {
            int rl0 = wm * 32 + mt * 16 + gq;
#pragma unroll
            for (int nt = 0; nt < 4; nt++) {
                int col = wn * 32 + nt * 8 + 2 * tq;
                float e0 = __expf(sacc[mt][nt][0] - nmax[mt][0]);
                float e1 = __expf(sacc[mt][nt][1] - nmax[mt][0]);
                float e2 = __expf(sacc[mt][nt][2] - nmax[mt][1]);
                float e3 = __expf(sacc[mt][nt][3] - nmax[mt][1]);
                Ps[rl0][col] = e0;     Ps[rl0][col + 1] = e1;
                Ps[rl0 + 8][col] = e2; Ps[rl0 + 8][col + 1] = e3;
                lsum[mt][0] += e0 + e1; lsum[mt][1] += e2 + e3;
            }
        }
#pragma unroll
        for (int mt = 0; mt < 2; mt++)
#pragma unroll
            for (int h = 0; h < 2; h++) {
                lsum[mt][h] += __shfl_xor_sync(0xffffffffu, lsum[mt][h], 1);
                lsum[mt][h] += __shfl_xor_sync(0xffffffffu, lsum[mt][h], 2);
            }
        __syncthreads();
        if (tq == 0)
#pragma unroll
            for (int mt = 0; mt < 2; mt++)
#pragma unroll
                for (int h = 0; h < 2; h++)
                    red[wn][wm * 32 + mt * 16 + gq + 8 * h] = lsum[mt][h];
        __syncthreads();
#pragma unroll
        for (int mt = 0; mt < 2; mt++)
#pragma unroll
            for (int h = 0; h < 2; h++) {
                int rl = wm * 32 + mt * 16 + gq + 8 * h;
                float cs = red[0][rl] + red[1][rl] + red[2][rl] + red[3][rl];
                rsum[mt][h] = rsum[mt][h] * fct[mt][h] + cs;
            }
#pragma unroll
        for (int mt = 0; mt < 2; mt++)
#pragma unroll
            for (int nt = 0; nt < 8; nt++) {
                oacc[mt][nt][0] *= fct[mt][0]; oacc[mt][nt][1] *= fct[mt][0];
                oacc[mt][nt][2] *= fct[mt][1]; oacc[mt][nt][3] *= fct[mt][1];
            }

        // O += P @ G
        for (int ks = 0; ks < 4; ks++) {
            __syncthreads();
#pragma unroll
            for (int p = 0; p < 8; p++) {
                int idx = tid + p * 256, r = idx >> 6, c4 = (idx & 63) << 2;
                *(float4*)&Gs[r][c4] =
                    *(const float4*)(g_gv + ((size_t)b * 1024 + mc0 + ks * 32 + r) * 256 + c4);
            }
            __syncthreads();
#pragma unroll
            for (int k8 = 0; k8 < 4; k8++) {
                const int kg = ks * 32 + k8 * 8;
                unsigned af[2][4], bf[8][2];
#pragma unroll
                for (int mt = 0; mt < 2; mt++) {
                    int rl = wm * 32 + mt * 16 + gq;
                    af[mt][0] = f2tf(Ps[rl][kg + tq]);
                    af[mt][1] = f2tf(Ps[rl + 8][kg + tq]);
                    af[mt][2] = f2tf(Ps[rl][kg + tq + 4]);
                    af[mt][3] = f2tf(Ps[rl + 8][kg + tq + 4]);
                }
#pragma unroll
                for (int nt = 0; nt < 8; nt++) {
                    int co = wn * 64 + nt * 8 + gq;
                    bf[nt][0] = f2tf(Gs[k8 * 8 + tq][co]);
                    bf[nt][1] = f2tf(Gs[k8 * 8 + tq + 4][co]);
                }
#pragma unroll
                for (int mt = 0; mt < 2; mt++)
#pragma unroll
                    for (int nt = 0; nt < 8; nt++)
                        mma_tf32(oacc[mt][nt], af[mt], bf[nt]);
            }
        }
    }

    float inv[2][2];
#pragma unroll
    for (int mt = 0; mt < 2; mt++)
#pragma unroll
        for (int h = 0; h < 2; h++) inv[mt][h] = 1.0f / rsum[mt][h];
#pragma unroll
    for (int mt = 0; mt < 2; mt++) {
        int rl = wm * 32 + mt * 16 + gq;
#pragma unroll
        for (int nt = 0; nt < 8; nt++) {
            int co = wn * 64 + nt * 8 + 2 * tq;
            float2 v0 = make_float2(oacc[mt][nt][0] * inv[mt][0], oacc[mt][nt][1] * inv[mt][0]);
            float2 v1 = make_float2(oacc[mt][nt][2] * inv[mt][1], oacc[mt][nt][3] * inv[mt][1]);
            *(float2*)(g_ag + ((size_t)b * 4096 + p0 + rl) * 256 + co) = v0;
            *(float2*)(g_ag + ((size_t)b * 4096 + p0 + rl + 8) * 256 + co) = v1;
        }
    }
}

// ---------------------------------------------------------------------------
// Final conv + residual. M-side = 128 positions (ag rows), N-side = 128
// channels (w_attn rows consumed as col-major B). K=256, plain tf32.
// ---------------------------------------------------------------------------
__global__ void __launch_bounds__(256)
out_kernel(const float* __restrict__ x, const float* __restrict__ wA,
           const float* __restrict__ bA, const float* __restrict__ sigma,
           float* __restrict__ out)
{
    __shared__ float As[128][36];
    __shared__ float Ws[128][36];
    const int tid = threadIdx.x, lane = tid & 31, wid = tid >> 5;
    const int gq = lane >> 2, tq = lane & 3;
    const int wm = wid & 1, wn = wid >> 1;
    const int b = blockIdx.z, p00 = blockIdx.x * 128, c00 = blockIdx.y * 128;

    float acc[4][4][4];
#pragma unroll
    for (int i = 0; i < 4; i++)
#pragma unroll
        for (int j = 0; j < 4; j++)
#pragma unroll
            for (int k = 0; k < 4; k++) acc[i][j][k] = 0.f;

    for (int k0 = 0; k0 < 256; k0 += 32) {
#pragma unroll
        for (int p = 0; p < 4; p++) {
            int idx = tid + p * 256, r = idx >> 3, c4 = (idx & 7) << 2;
            *(float4*)&As[r][c4] = *(const float4*)(g_ag + ((size_t)b * 4096 + p00 + r) * 256 + k0 + c4);
            *(float4*)&Ws[r][c4] = *(const float4*)(wA + (size_t)(c00 + r) * 256 + k0 + c4);
        }
        __syncthreads();
#pragma unroll
        for (int k8 = 0; k8 < 4; k8++) {
            const int kk = k8 * 8;
            unsigned af[4][4], bf[4][2];
#pragma unroll
            for (int mt = 0; mt < 4; mt++) {
                int r0 = wm * 64 + mt * 16 + gq;
                af[mt][0] = f2tf(As[r0][kk + tq]);     af[mt][1] = f2tf(As[r0 + 8][kk + tq]);
                af[mt][2] = f2tf(As[r0][kk + tq + 4]); af[mt][3] = f2tf(As[r0 + 8][kk + tq + 4]);
            }
#pragma unroll
            for (int nt = 0; nt < 4; nt++) {
                int c0 = wn * 32 + nt * 8 + gq;
                bf[nt][0] = f2tf(Ws[c0][kk + tq]);
                bf[nt][1] = f2tf(Ws[c0][kk + tq + 4]);
            }
#pragma unroll
            for (int mt = 0; mt < 4; mt++)
#pragma unroll
                for (int nt = 0; nt < 4; nt++)
                    mma_tf32(acc[mt][nt], af[mt], bf[nt]);
        }
        __syncthreads();
    }

    const float sg = sigma[0];
#pragma unroll
    for (int mt = 0; mt < 4; mt++) {
        int p = p00 + wm * 64 + mt * 16 + gq;
#pragma unroll
        for (int nt = 0; nt < 4; nt++) {
            int c = c00 + wn * 32 + nt * 8 + 2 * tq;
            float bv0 = bA[c], bv1 = bA[c + 1];
            size_t i00 = ((size_t)b * 512 + c) * 4096 + p;
            out[i00]          = x[i00]          + sg * (acc[mt][nt][0] + bv0);
            out[i00 + 4096]   = x[i00 + 4096]   + sg * (acc[mt][nt][1] + bv1);
            out[i00 + 8]        = x[i00 + 8]        + sg * (acc[mt][nt][2] + bv0);
            out[i00 + 4096 + 8] = x[i00 + 4096 + 8] + sg * (acc[mt][nt][3] + bv1);
        }
    }
}

extern "C" void kernel_launch(void* const* d_in, const int* in_sizes, int n_in,
                              void* d_out, int out_size)
{
    const float* x       = (const float*)d_in[0];
    const float* w_theta = (const float*)d_in[1];
    const float* b_theta = (const float*)d_in[2];
    const float* w_phi   = (const float*)d_in[3];
    const float* b_phi   = (const float*)d_in[4];
    const float* w_g     = (const float*)d_in[5];
    const float* b_g     = (const float*)d_in[6];
    const float* w_attn  = (const float*)d_in[7];
    const float* b_attn  = (const float*)d_in[8];
    const float* sigma   = (const float*)d_in[9];
    float* out = (float*)d_out;

    static int smem_set = 0;
    const int attn_smem = (64 * 68 + 64 * 132 + 64 * 132 + 4 * 64) * 4;  // 86016
    if (!smem_set) {
        cudaFuncSetAttribute(attn_kernel, cudaFuncAttributeMaxDynamicSharedMemorySize, attn_smem);
        smem_set = 1;
    }

    conv_kernel<0><<<dim3(32, 1, NB), 256>>>(x, w_theta, w_phi, b_theta, b_phi);
    conv_kernel<1><<<dim3(32, 2, NB), 256>>>(x, w_g, nullptr, b_g, nullptr);
    attn_kernel<<<dim3(64, NB), 256, attn_smem>>>();
    out_kernel<<<dim3(32, 4, NB), 256>>>(x, w_attn, b_attn, sigma, out);
}